// round 15
// baseline (speedup 1.0000x reference)
#include <cuda_runtime.h>
#include <cuda_fp16.h>
#include <math.h>
#include <float.h>
#include <stdint.h>

// ---------------------------------------------------------------------------
// NCM few-shot classifier — approximate-then-verify tensor-core pipeline.
//   1) mean over support rows (2-stage deterministic)
//   2) pack: center+normalize; write fp16(hi) rows (K=512) + fp32 normalized
//   3) GEMM: PERSISTENT blocks; flat chunk loop over all assigned 128x128
//      tiles with a seamless 3-stage cp.async ring (no drain at tile edges);
//      per-tile TOP-2 (v1,i1,v2) per query written to [q][split] records
//   4) pick: warp per query; sound threshold TH=2.5e-3 (> 2x worst-case fp16
//      error ~1.1e-3 on unit vectors); singles -> one exact fp32 rescore,
//      rare dense splits -> full split rescore. Class = best/SHOTS as float.
// ---------------------------------------------------------------------------

#define DIMK    512
#define KP      512
#define SHOTS   5
#define QT      128
#define ST      128
#define CH      64
#define CPT     8              // chunks per tile (KP/CH)
#define ROWB    144
#define MAXV    5120
#define MAXSPLIT 40
#define MEANBLK 160
#define TH      2.5e-3f
#define GMAX    296            // 2 CTAs/SM x 148 SMs

#define SM_BUF(b)  ((b) * 36864)
#define SM_BOFF    18432
#define SM_TOTAL   110592

__device__ __align__(16) float  g_part[MEANBLK][DIMK];
__device__ __align__(16) float  g_mean[DIMK];
__device__ __align__(16) __half g_qh[(size_t)MAXV * KP];
__device__ __align__(16) __half g_sh[(size_t)MAXV * KP];
__device__ __align__(16) float  g_qnf[(size_t)MAXV * DIMK];
__device__ __align__(16) float  g_snf[(size_t)MAXV * DIMK];
__device__ __align__(16) float  g_b1v[(size_t)MAXV * MAXSPLIT];
__device__ __align__(16) int    g_b1i[(size_t)MAXV * MAXSPLIT];
__device__ __align__(16) float  g_b2v[(size_t)MAXV * MAXSPLIT];

// ---- PTX helpers -------------------------------------------------------------
__device__ __forceinline__ uint32_t smem_u32(const void* p) {
    uint32_t a;
    asm("{ .reg .u64 t; cvta.to.shared.u64 t, %1; cvt.u32.u64 %0, t; }"
        : "=r"(a) : "l"(p));
    return a;
}
__device__ __forceinline__ void cp16(uint32_t dst, const void* src) {
    uint64_t g;
    asm("cvta.to.global.u64 %0, %1;" : "=l"(g) : "l"(src));
    asm volatile("cp.async.cg.shared.global [%0], [%1], 16;"
                 :: "r"(dst), "l"(g) : "memory");
}
__device__ __forceinline__ void cp_commit() {
    asm volatile("cp.async.commit_group;" ::: "memory");
}
template <int N>
__device__ __forceinline__ void cp_wait() {
    asm volatile("cp.async.wait_group %0;" :: "n"(N) : "memory");
}
__device__ __forceinline__ void ldsm_x4(uint32_t& r0, uint32_t& r1,
                                        uint32_t& r2, uint32_t& r3, uint32_t a) {
    asm volatile("ldmatrix.sync.aligned.m8n8.x4.shared.b16 {%0,%1,%2,%3}, [%4];"
                 : "=r"(r0), "=r"(r1), "=r"(r2), "=r"(r3) : "r"(a));
}
__device__ __forceinline__ void mma16816(float* c, const uint32_t* a,
                                         uint32_t b0, uint32_t b1) {
    asm volatile(
        "mma.sync.aligned.m16n8k16.row.col.f32.f16.f16.f32 "
        "{%0,%1,%2,%3}, {%4,%5,%6,%7}, {%8,%9}, {%0,%1,%2,%3};"
        : "+f"(c[0]), "+f"(c[1]), "+f"(c[2]), "+f"(c[3])
        : "r"(a[0]), "r"(a[1]), "r"(a[2]), "r"(a[3]), "r"(b0), "r"(b1));
}

// --- stage 1/2: deterministic support mean -------------------------------------
__global__ void k_mean_part(const float* __restrict__ s, int nrows) {
    int b  = blockIdx.x;
    int d0 = threadIdx.x, d1 = threadIdx.x + 256;
    float a0 = 0.0f, a1 = 0.0f;
    for (int r = b; r < nrows; r += MEANBLK) {
        const float* row = s + (size_t)r * DIMK;
        a0 += row[d0]; a1 += row[d1];
    }
    g_part[b][d0] = a0; g_part[b][d1] = a1;
}
__global__ void k_mean_final(float inv_cnt) {
    int d0 = threadIdx.x, d1 = threadIdx.x + 256;
    float a0 = 0.0f, a1 = 0.0f;
    for (int b = 0; b < MEANBLK; ++b) { a0 += g_part[b][d0]; a1 += g_part[b][d1]; }
    g_mean[d0] = a0 * inv_cnt; g_mean[d1] = a1 * inv_cnt;
}

// --- stage 3: center + normalize; emit fp16(hi) + fp32 rows (warp per row) -----
__global__ void k_pack(const float* __restrict__ sup, const float* __restrict__ qry,
                       int nsup, int nq) {
    int gw   = blockIdx.x * 8 + (threadIdx.x >> 5);
    int lane = threadIdx.x & 31;
    if (gw >= 2 * MAXV) return;
    bool isQ = (gw >= MAXV);
    int  row = isQ ? gw - MAXV : gw;
    __half* dh = (isQ ? g_qh : g_sh) + (size_t)row * KP;
    float*  df = (isQ ? g_qnf : g_snf) + (size_t)row * DIMK;
    bool valid = isQ ? (row < nq) : (row < nsup);
    if (!valid) {
        uint4 z = make_uint4(0, 0, 0, 0);
        for (int i = lane; i < (KP * 2) / 16; i += 32) ((uint4*)dh)[i] = z;
        return;
    }
    const float* src = (isQ ? qry : sup) + (size_t)row * DIMK;
    float v[16], nrm = 0.0f;
    #pragma unroll
    for (int i = 0; i < 16; ++i) {
        int k = i * 32 + lane;
        v[i] = src[k] - g_mean[k];
        nrm += v[i] * v[i];
    }
    #pragma unroll
    for (int o = 16; o; o >>= 1) nrm += __shfl_xor_sync(0xffffffffu, nrm, o);
    float rn = 1.0f / sqrtf(nrm);
    #pragma unroll
    for (int i = 0; i < 16; ++i) {
        int k = i * 32 + lane;
        float n = v[i] * rn;
        dh[k] = __float2half(n);
        df[k] = n;
    }
}

// --- stage 4: persistent mma.sync GEMM, seamless 3-stage ring -------------------
__device__ __forceinline__ void stage_chunk(uint32_t sb, const char* smemc,
                                            int buf, int gt, int kc,
                                            int nts, int tid) {
    const int q0   = (gt / nts) * QT;
    const int sbeg = (gt % nts) * ST;
    const int ko2  = kc * CH * 2;
    uint32_t ab = sb + SM_BUF(buf);
    uint32_t bb = ab + SM_BOFF;
    (void)smemc;
    #pragma unroll
    for (int l = 0; l < 4; ++l) {
        int idx = tid + l * 256;
        int row = idx >> 3, p = idx & 7;
        cp16(ab + row * ROWB + p * 16,
             (const char*)(g_qh + (size_t)(q0 + row) * KP) + ko2 + p * 16);
        cp16(bb + row * ROWB + p * 16,
             (const char*)(g_sh + (size_t)(sbeg + row) * KP) + ko2 + p * 16);
    }
}

__global__ void __launch_bounds__(256, 2)
k_mma_best(int nq, int ns, int ntq, int nts) {
    extern __shared__ __align__(16) char smem[];
    const uint32_t sb = smem_u32(smem);
    const int tid   = threadIdx.x;
    const int lane  = tid & 31;
    const int warp  = tid >> 5;
    const int warpm = warp >> 1;
    const int warpn = warp & 1;
    const int G     = gridDim.x;
    const int ntiles = ntq * nts;

    // number of tiles this block owns
    int nt = 0;
    for (int t = blockIdx.x; t < ntiles; t += G) ++nt;
    if (nt == 0) return;
    const int total = nt * CPT;

    float acc[2][8][4];
    #pragma unroll
    for (int mt = 0; mt < 2; ++mt)
        #pragma unroll
        for (int ntt = 0; ntt < 8; ++ntt)
            #pragma unroll
            for (int e = 0; e < 4; ++e) acc[mt][ntt][e] = 0.0f;

    // prologue: stage chunks 0 and 1
    stage_chunk(sb, smem, 0, blockIdx.x, 0, nts, tid);
    cp_commit();
    if (total > 1)
        stage_chunk(sb, smem, 1, blockIdx.x + (1 / CPT) * G, 1 % CPT, nts, tid);
    cp_commit();

    const int r = lane & 7, g = lane >> 3;
    const int m0 = warpm * 32, n0 = warpn * 64;
    const int group = lane >> 2, tg = lane & 3;

    for (int c = 0; c < total; ++c) {
        if (c + 1 < total) cp_wait<1>(); else cp_wait<0>();
        __syncthreads();                    // chunk c resident; epilogue scratch free

        if (c + 2 < total) {
            int c2 = c + 2;
            stage_chunk(sb, smem, c2 % 3, blockIdx.x + (c2 / CPT) * G,
                        c2 % CPT, nts, tid);
        }
        cp_commit();                        // uniform group count per iteration

        uint32_t ab = sb + SM_BUF(c % 3);
        uint32_t bb = ab + SM_BOFF;
        #pragma unroll
        for (int ks = 0; ks < 4; ++ks) {
            const int k0 = ks * 16;
            uint32_t a[2][4];
            #pragma unroll
            for (int mt = 0; mt < 2; ++mt) {
                uint32_t addr = ab + (m0 + mt * 16 + ((g & 1) << 3) + r) * ROWB
                                   + (k0 + ((g >> 1) << 3)) * 2;
                ldsm_x4(a[mt][0], a[mt][1], a[mt][2], a[mt][3], addr);
            }
            #pragma unroll
            for (int np = 0; np < 4; ++np) {
                uint32_t b0, b1, b2, b3;
                uint32_t addr = bb + (n0 + np * 16 + ((g >> 1) << 3) + r) * ROWB
                                   + (k0 + ((g & 1) << 3)) * 2;
                ldsm_x4(b0, b1, b2, b3, addr);
                #pragma unroll
                for (int mt = 0; mt < 2; ++mt) {
                    mma16816(acc[mt][np * 2 + 0], a[mt], b0, b1);
                    mma16816(acc[mt][np * 2 + 1], a[mt], b2, b3);
                }
            }
        }

        if ((c & (CPT - 1)) == (CPT - 1)) {
            // ---- tile epilogue: TOP-2 over this tile, using freed ring buf ------
            const int gt   = blockIdx.x + (c / CPT) * G;
            const int q0   = (gt / nts) * QT;
            const int sbeg = (gt % nts) * ST;
            const int sp   = gt % nts;

            float v1[4], v2[4];
            int   i1[4];
            #pragma unroll
            for (int i = 0; i < 4; ++i) { v1[i] = -FLT_MAX; v2[i] = -FLT_MAX; i1[i] = MAXV; }

            #pragma unroll
            for (int mt = 0; mt < 2; ++mt)
                #pragma unroll
                for (int ntt = 0; ntt < 8; ++ntt) {
                    int c0 = sbeg + n0 + ntt * 8 + tg * 2;
                    #pragma unroll
                    for (int h = 0; h < 2; ++h) {
                        int i = mt * 2 + h;
                        float a0 = acc[mt][ntt][h * 2 + 0];
                        float a1 = acc[mt][ntt][h * 2 + 1];
                        if (c0 < ns) {
                            if (a0 > v1[i]) { v2[i] = v1[i]; v1[i] = a0; i1[i] = c0; }
                            else if (a0 > v2[i]) v2[i] = a0;
                        }
                        if (c0 + 1 < ns) {
                            if (a1 > v1[i]) { v2[i] = v1[i]; v1[i] = a1; i1[i] = c0 + 1; }
                            else if (a1 > v2[i]) v2[i] = a1;
                        }
                        acc[mt][ntt][h * 2 + 0] = 0.0f;   // re-zero for next tile
                        acc[mt][ntt][h * 2 + 1] = 0.0f;
                    }
                }
            #pragma unroll
            for (int o = 1; o < 4; o <<= 1) {
                #pragma unroll
                for (int i = 0; i < 4; ++i) {
                    float ov1 = __shfl_xor_sync(0xffffffffu, v1[i], o);
                    int   oi1 = __shfl_xor_sync(0xffffffffu, i1[i], o);
                    float ov2 = __shfl_xor_sync(0xffffffffu, v2[i], o);
                    if (ov1 > v1[i] || (ov1 == v1[i] && oi1 < i1[i])) {
                        v2[i] = fmaxf(v1[i], ov2); v1[i] = ov1; i1[i] = oi1;
                    } else {
                        v2[i] = fmaxf(v2[i], ov1);
                    }
                }
            }
            // scratch in the just-freed ring buffer c%3 (in-flight bufs are the others)
            char* eb = smem + SM_BUF(c % 3);
            float* s_v1 = (float*)(eb);
            int*   s_i1 = (int*)(eb + 1024);
            float* s_v2 = (float*)(eb + 2048);
            if (tg == 0) {
                #pragma unroll
                for (int mt = 0; mt < 2; ++mt)
                    #pragma unroll
                    for (int h = 0; h < 2; ++h) {
                        int row = m0 + mt * 16 + h * 8 + group;
                        s_v1[row * 2 + warpn] = v1[mt * 2 + h];
                        s_i1[row * 2 + warpn] = i1[mt * 2 + h];
                        s_v2[row * 2 + warpn] = v2[mt * 2 + h];
                    }
            }
            __syncthreads();
            if (tid < QT) {
                float a1v = s_v1[tid * 2 + 0], a2v = s_v2[tid * 2 + 0];
                int   a1i = s_i1[tid * 2 + 0];
                float b1v = s_v1[tid * 2 + 1], b2v = s_v2[tid * 2 + 1];
                int   b1i = s_i1[tid * 2 + 1];
                float o1, o2; int oi;
                if (b1v > a1v || (b1v == a1v && b1i < a1i)) {
                    o1 = b1v; oi = b1i; o2 = fmaxf(a1v, b2v);
                } else {
                    o1 = a1v; oi = a1i; o2 = fmaxf(a2v, b1v);
                }
                int q = q0 + tid;
                if (q < nq) {
                    size_t rec = (size_t)q * MAXSPLIT + sp;
                    g_b1v[rec] = o1;
                    g_b1i[rec] = oi;
                    g_b2v[rec] = o2;
                }
            }
            // smem reuse protected by the top-of-loop __syncthreads next iteration
        }
    }
}

// --- stage 5: pick — warp per query; threshold, exact rescore, classify --------
__global__ void __launch_bounds__(256)
k_pick(float* __restrict__ out, int nq, int ns, int nsp, int out_size) {
    const int lane = threadIdx.x & 31;
    const int q = blockIdx.x * 8 + (threadIdx.x >> 5);
    if (q >= nq) {
        if (q < out_size && lane == 0) out[q] = 0.0f;
        return;
    }
    // load split records: lane handles splits lane and lane+32
    size_t base = (size_t)q * MAXSPLIT;
    bool okA = lane < nsp, okB = lane + 32 < nsp;
    float va = okA ? g_b1v[base + lane]      : -FLT_MAX;
    int   ia = okA ? g_b1i[base + lane]      : MAXV;
    float wa = okA ? g_b2v[base + lane]      : -FLT_MAX;
    float vb = okB ? g_b1v[base + lane + 32] : -FLT_MAX;
    int   ib = okB ? g_b1i[base + lane + 32] : MAXV;
    float wb = okB ? g_b2v[base + lane + 32] : -FLT_MAX;

    float mx = fmaxf(va, vb);
    #pragma unroll
    for (int o = 16; o; o >>= 1) mx = fmaxf(mx, __shfl_xor_sync(0xffffffffu, mx, o));
    float th = mx - TH;

    const float* qv = g_qnf + (size_t)q * DIMK;
    float bv = -FLT_MAX;
    int   bi = MAXV;

    #pragma unroll
    for (int half = 0; half < 2; ++half) {
        float v1 = half ? vb : va;
        float v2 = half ? wb : wa;
        int   i1 = half ? ib : ia;
        unsigned cmask = __ballot_sync(0xffffffffu, v1 >= th);
        while (cmask) {
            int ln = __ffs(cmask) - 1;
            cmask &= cmask - 1;
            float sv2 = __shfl_sync(0xffffffffu, v2, ln);
            int  cand = __shfl_sync(0xffffffffu, i1, ln);
            if (sv2 >= th) {
                // dense split: exact rescore of all its supports
                int spl = ln + half * 32;
                int s0 = spl * ST, s1 = min(s0 + ST, ns);
                for (int s = s0; s < s1; ++s) {
                    const float* sv = g_snf + (size_t)s * DIMK;
                    float d = 0.0f;
                    #pragma unroll
                    for (int i = 0; i < 16; ++i)
                        d += qv[i * 32 + lane] * sv[i * 32 + lane];
                    #pragma unroll
                    for (int o = 16; o; o >>= 1)
                        d += __shfl_xor_sync(0xffffffffu, d, o);
                    if (d > bv || (d == bv && s < bi)) { bv = d; bi = s; }
                }
            } else {
                const float* sv = g_snf + (size_t)cand * DIMK;
                float d = 0.0f;
                #pragma unroll
                for (int i = 0; i < 16; ++i)
                    d += qv[i * 32 + lane] * sv[i * 32 + lane];
                #pragma unroll
                for (int o = 16; o; o >>= 1)
                    d += __shfl_xor_sync(0xffffffffu, d, o);
                if (d > bv || (d == bv && cand < bi)) { bv = d; bi = cand; }
            }
        }
    }
    if (lane == 0) out[q] = (float)(bi / SHOTS);
}

// ---------------------------------------------------------------------------
extern "C" void kernel_launch(void* const* d_in, const int* in_sizes, int n_in,
                              void* d_out, int out_size) {
    const float* sup = (const float*)d_in[0];   // support_features [1000,5,512]
    const float* qry = (const float*)d_in[1];   // query_features   [5000,512]
    // d_in[2] = use_cosine: ignored (decision is mathematically identical)

    int nsup = in_sizes[0] / DIMK;
    int nq   = in_sizes[1] / DIMK;
    if (nsup > MAXV) nsup = MAXV;
    if (nq   > MAXV) nq   = MAXV;
    if (nsup < 1) nsup = 1;
    if (nq   < 1) nq   = 1;
    if (nq > out_size) nq = out_size;

    k_mean_part<<<MEANBLK, 256>>>(sup, nsup);
    k_mean_final<<<1, 256>>>(1.0f / (float)nsup);

    k_pack<<<(2 * MAXV) / 8, 256>>>(sup, qry, nsup, nq);

    int ntq = (nq + QT - 1) / QT;               // 40
    int nts = (nsup + ST - 1) / ST;             // 40
    if (nts > MAXSPLIT) nts = MAXSPLIT;
    int ntiles = ntq * nts;                     // 1600
    int G = (ntiles < GMAX) ? ntiles : GMAX;    // 296 persistent blocks

    cudaFuncSetAttribute(k_mma_best,
                         cudaFuncAttributeMaxDynamicSharedMemorySize, SM_TOTAL);
    k_mma_best<<<G, 256, SM_TOTAL>>>(nq, nsup, ntq, nts);

    int cover = (out_size > nq) ? out_size : nq;
    k_pick<<<(cover + 7) / 8, 256>>>((float*)d_out, nq, nsup, nts, out_size);
}

// round 16
// speedup vs baseline: 1.5635x; 1.5635x over previous
#include <cuda_runtime.h>
#include <cuda_fp16.h>
#include <math.h>
#include <float.h>
#include <stdint.h>

// ---------------------------------------------------------------------------
// NCM few-shot classifier — approximate-then-verify tensor-core pipeline.
//   1) mean over support rows (2-stage deterministic)
//   2) pack: center+normalize; write fp16(hi) rows (K=512) + per-row inv-norm
//   3) GEMM: fp16 pass via mma.sync m16n8k16 (r13 chassis, measured 88 us);
//      per-split TOP-2 (v1,i1,v2) per query
//   4) pick: global approx max; sound threshold TH=2.5e-3 (> 2x worst-case
//      fp16 error ~1.1e-3 on unit vectors). v1<th splits are provably out;
//      v1>=th,v2<th -> one exact fp32 rescore (recomputed from RAW inputs,
//      bit-identical arithmetic to storing normalized rows); v2>=th (rare)
//      -> rescore whole split. Class = best/SHOTS as float32.
// ---------------------------------------------------------------------------

#define DIMK    512
#define KP      512
#define SHOTS   5
#define QT      128
#define ST      128
#define CH      64
#define NCHUNK  (KP / CH)     // 8
#define ROWB    144
#define MAXV    5120
#define MAXSPLIT 40
#define MEANBLK 64
#define TH      2.5e-3f

// dynamic smem layout (bytes)
#define SM_ABUF(b) ((b) * 36864)
#define SM_BBUF(b) ((b) * 36864 + 18432)
#define SM_SV1     73728
#define SM_SI1     74752
#define SM_SV2     75776
#define SM_TOTAL   76800

__device__ __align__(16) float  g_part[MEANBLK][DIMK];
__device__ __align__(16) float  g_mean[DIMK];
__device__ __align__(16) __half g_qh[(size_t)MAXV * KP];
__device__ __align__(16) __half g_sh[(size_t)MAXV * KP];
__device__ __align__(16) float  g_rn[2 * MAXV];        // [s], [MAXV+q] inv-norms
__device__ __align__(16) float  g_b1v[(size_t)MAXV * MAXSPLIT];
__device__ __align__(16) int    g_b1i[(size_t)MAXV * MAXSPLIT];
__device__ __align__(16) float  g_b2v[(size_t)MAXV * MAXSPLIT];

// ---- PTX helpers -------------------------------------------------------------
__device__ __forceinline__ uint32_t smem_u32(const void* p) {
    uint32_t a;
    asm("{ .reg .u64 t; cvta.to.shared.u64 t, %1; cvt.u32.u64 %0, t; }"
        : "=r"(a) : "l"(p));
    return a;
}
__device__ __forceinline__ void cp16(uint32_t dst, const void* src) {
    uint64_t g;
    asm("cvta.to.global.u64 %0, %1;" : "=l"(g) : "l"(src));
    asm volatile("cp.async.cg.shared.global [%0], [%1], 16;"
                 :: "r"(dst), "l"(g) : "memory");
}
__device__ __forceinline__ void cp_commit() {
    asm volatile("cp.async.commit_group;" ::: "memory");
}
template <int N>
__device__ __forceinline__ void cp_wait() {
    asm volatile("cp.async.wait_group %0;" :: "n"(N) : "memory");
}
__device__ __forceinline__ void ldsm_x4(uint32_t& r0, uint32_t& r1,
                                        uint32_t& r2, uint32_t& r3, uint32_t a) {
    asm volatile("ldmatrix.sync.aligned.m8n8.x4.shared.b16 {%0,%1,%2,%3}, [%4];"
                 : "=r"(r0), "=r"(r1), "=r"(r2), "=r"(r3) : "r"(a));
}
__device__ __forceinline__ void mma16816(float* c, const uint32_t* a,
                                         uint32_t b0, uint32_t b1) {
    asm volatile(
        "mma.sync.aligned.m16n8k16.row.col.f32.f16.f16.f32 "
        "{%0,%1,%2,%3}, {%4,%5,%6,%7}, {%8,%9}, {%0,%1,%2,%3};"
        : "+f"(c[0]), "+f"(c[1]), "+f"(c[2]), "+f"(c[3])
        : "r"(a[0]), "r"(a[1]), "r"(a[2]), "r"(a[3]), "r"(b0), "r"(b1));
}

// --- stage 1/2: deterministic support mean -------------------------------------
__global__ void k_mean_part(const float* __restrict__ s, int nrows) {
    int b  = blockIdx.x;
    int d0 = threadIdx.x, d1 = threadIdx.x + 256;
    float a0 = 0.0f, a1 = 0.0f;
    for (int r = b; r < nrows; r += MEANBLK) {
        const float* row = s + (size_t)r * DIMK;
        a0 += row[d0]; a1 += row[d1];
    }
    g_part[b][d0] = a0; g_part[b][d1] = a1;
}
__global__ void k_mean_final(float inv_cnt) {
    int d0 = threadIdx.x, d1 = threadIdx.x + 256;
    float a0 = 0.0f, a1 = 0.0f;
    #pragma unroll 8
    for (int b = 0; b < MEANBLK; ++b) { a0 += g_part[b][d0]; a1 += g_part[b][d1]; }
    g_mean[d0] = a0 * inv_cnt; g_mean[d1] = a1 * inv_cnt;
}

// --- stage 3: center + normalize; emit fp16(hi) rows + inv-norm ----------------
__global__ void k_pack(const float* __restrict__ sup, const float* __restrict__ qry,
                       int nsup, int nq) {
    int gw   = blockIdx.x * 8 + (threadIdx.x >> 5);
    int lane = threadIdx.x & 31;
    if (gw >= 2 * MAXV) return;
    bool isQ = (gw >= MAXV);
    int  row = isQ ? gw - MAXV : gw;
    __half* dh = (isQ ? g_qh : g_sh) + (size_t)row * KP;
    bool valid = isQ ? (row < nq) : (row < nsup);
    if (!valid) {                          // zero fp16 pad rows (MMA operands)
        uint4 z = make_uint4(0, 0, 0, 0);
        for (int i = lane; i < (KP * 2) / 16; i += 32) ((uint4*)dh)[i] = z;
        return;
    }
    const float* src = (isQ ? qry : sup) + (size_t)row * DIMK;
    float v[16], nrm = 0.0f;
    #pragma unroll
    for (int i = 0; i < 16; ++i) {
        int k = i * 32 + lane;
        v[i] = src[k] - g_mean[k];
        nrm += v[i] * v[i];
    }
    #pragma unroll
    for (int o = 16; o; o >>= 1) nrm += __shfl_xor_sync(0xffffffffu, nrm, o);
    float rn = 1.0f / sqrtf(nrm);
    #pragma unroll
    for (int i = 0; i < 16; ++i) {
        int k = i * 32 + lane;
        dh[k] = __float2half(v[i] * rn);
    }
    if (lane == 0) g_rn[isQ ? (MAXV + row) : row] = rn;
}

// --- stage 4: mma.sync GEMM (128x128) + per-split TOP-2 epilogue (r13) ----------
__device__ __forceinline__ void stage_chunk(uint32_t sb, int buf, int kc,
                                            int q0, int sbeg, int tid) {
    const int ko2 = kc * CH * 2;
    uint32_t ab = sb + SM_ABUF(buf);
    uint32_t bb = sb + SM_BBUF(buf);
    #pragma unroll
    for (int l = 0; l < 4; ++l) {
        int idx = tid + l * 256;
        int row = idx >> 3, p = idx & 7;
        cp16(ab + row * ROWB + p * 16,
             (const char*)(g_qh + (size_t)(q0 + row) * KP) + ko2 + p * 16);
        cp16(bb + row * ROWB + p * 16,
             (const char*)(g_sh + (size_t)(sbeg + row) * KP) + ko2 + p * 16);
    }
}

__global__ void __launch_bounds__(256, 2)
k_mma_best(int nq, int ns) {
    extern __shared__ __align__(16) char smem[];
    const uint32_t sb = smem_u32(smem);
    const int tid   = threadIdx.x;
    const int lane  = tid & 31;
    const int warp  = tid >> 5;
    const int warpm = warp >> 1;
    const int warpn = warp & 1;
    const int q0    = blockIdx.x * QT;
    const int sbeg  = blockIdx.y * ST;

    float acc[2][8][4];
    #pragma unroll
    for (int mt = 0; mt < 2; ++mt)
        #pragma unroll
        for (int nt = 0; nt < 8; ++nt)
            #pragma unroll
            for (int e = 0; e < 4; ++e) acc[mt][nt][e] = 0.0f;

    stage_chunk(sb, 0, 0, q0, sbeg, tid);
    cp_commit();

    const int r = lane & 7, g = lane >> 3;
    const int m0 = warpm * 32, n0 = warpn * 64;

    for (int kc = 0; kc < NCHUNK; ++kc) {
        const int cur = kc & 1;
        if (kc + 1 < NCHUNK) {
            stage_chunk(sb, cur ^ 1, kc + 1, q0, sbeg, tid);
            cp_commit();
            cp_wait<1>();
        } else {
            cp_wait<0>();
        }
        __syncthreads();

        uint32_t ab = sb + SM_ABUF(cur);
        uint32_t bb = sb + SM_BBUF(cur);
        #pragma unroll
        for (int ks = 0; ks < 4; ++ks) {
            const int k0 = ks * 16;
            uint32_t a[2][4];
            #pragma unroll
            for (int mt = 0; mt < 2; ++mt) {
                uint32_t addr = ab + (m0 + mt * 16 + ((g & 1) << 3) + r) * ROWB
                                   + (k0 + ((g >> 1) << 3)) * 2;
                ldsm_x4(a[mt][0], a[mt][1], a[mt][2], a[mt][3], addr);
            }
            #pragma unroll
            for (int np = 0; np < 4; ++np) {
                uint32_t b0, b1, b2, b3;
                uint32_t addr = bb + (n0 + np * 16 + ((g >> 1) << 3) + r) * ROWB
                                   + (k0 + ((g & 1) << 3)) * 2;
                ldsm_x4(b0, b1, b2, b3, addr);
                #pragma unroll
                for (int mt = 0; mt < 2; ++mt) {
                    mma16816(acc[mt][np * 2 + 0], a[mt], b0, b1);
                    mma16816(acc[mt][np * 2 + 1], a[mt], b2, b3);
                }
            }
        }
        __syncthreads();
    }

    // ---- epilogue: per-lane TOP-2 per owned row --------------------------------
    const int group = lane >> 2, tg = lane & 3;
    float v1[4], v2[4];
    int   i1[4];
    #pragma unroll
    for (int i = 0; i < 4; ++i) { v1[i] = -FLT_MAX; v2[i] = -FLT_MAX; i1[i] = MAXV; }

    #pragma unroll
    for (int mt = 0; mt < 2; ++mt)
        #pragma unroll
        for (int nt = 0; nt < 8; ++nt) {
            int c0 = sbeg + n0 + nt * 8 + tg * 2;
            #pragma unroll
            for (int h = 0; h < 2; ++h) {
                int i = mt * 2 + h;
                float a0 = acc[mt][nt][h * 2 + 0];
                float a1 = acc[mt][nt][h * 2 + 1];
                if (c0 < ns) {
                    if (a0 > v1[i]) { v2[i] = v1[i]; v1[i] = a0; i1[i] = c0; }
                    else if (a0 > v2[i]) v2[i] = a0;
                }
                if (c0 + 1 < ns) {
                    if (a1 > v1[i]) { v2[i] = v1[i]; v1[i] = a1; i1[i] = c0 + 1; }
                    else if (a1 > v2[i]) v2[i] = a1;
                }
            }
        }
    #pragma unroll
    for (int o = 1; o < 4; o <<= 1) {
        #pragma unroll
        for (int i = 0; i < 4; ++i) {
            float ov1 = __shfl_xor_sync(0xffffffffu, v1[i], o);
            int   oi1 = __shfl_xor_sync(0xffffffffu, i1[i], o);
            float ov2 = __shfl_xor_sync(0xffffffffu, v2[i], o);
            if (ov1 > v1[i] || (ov1 == v1[i] && oi1 < i1[i])) {
                v2[i] = fmaxf(v1[i], ov2); v1[i] = ov1; i1[i] = oi1;
            } else {
                v2[i] = fmaxf(v2[i], ov1);
            }
        }
    }
    float* s_v1 = (float*)(smem + SM_SV1);   // [128][2]
    int*   s_i1 = (int*)(smem + SM_SI1);
    float* s_v2 = (float*)(smem + SM_SV2);
    if (tg == 0) {
        #pragma unroll
        for (int mt = 0; mt < 2; ++mt)
            #pragma unroll
            for (int h = 0; h < 2; ++h) {
                int row = m0 + mt * 16 + h * 8 + group;
                s_v1[row * 2 + warpn] = v1[mt * 2 + h];
                s_i1[row * 2 + warpn] = i1[mt * 2 + h];
                s_v2[row * 2 + warpn] = v2[mt * 2 + h];
            }
    }
    __syncthreads();
    if (tid < QT) {
        float a1v = s_v1[tid * 2 + 0], a2v = s_v2[tid * 2 + 0];
        int   a1i = s_i1[tid * 2 + 0];
        float b1v = s_v1[tid * 2 + 1], b2v = s_v2[tid * 2 + 1];
        int   b1i = s_i1[tid * 2 + 1];
        float o1, o2; int oi;
        if (b1v > a1v || (b1v == a1v && b1i < a1i)) {
            o1 = b1v; oi = b1i; o2 = fmaxf(a1v, b2v);
        } else {
            o1 = a1v; oi = a1i; o2 = fmaxf(a2v, b1v);
        }
        int q = q0 + tid;
        if (q < nq) {
            size_t rec = (size_t)q * MAXSPLIT + blockIdx.y;
            g_b1v[rec] = o1;
            g_b1i[rec] = oi;
            g_b2v[rec] = o2;
        }
    }
}

// --- stage 5: pick — threshold, exact fp32 rescore from RAW inputs --------------
__global__ void __launch_bounds__(128)
k_pick(float* __restrict__ out,
       const float* __restrict__ sup, const float* __restrict__ qry,
       int nq, int ns, int nsp) {
    int q = blockIdx.x;
    const int tid  = threadIdx.x;
    if (q >= nq) { if (tid == 0) out[q] = 0.0f; return; }
    const int lane = tid & 31;
    const int warp = tid >> 5;

    __shared__ float ms[DIMK];          // mean
    __shared__ float qc[DIMK];          // (q - m) * rnq  (== stored qn of r13)
    __shared__ float sv1[MAXSPLIT], sv2[MAXSPLIT];
    __shared__ int   si1[MAXSPLIT];
    __shared__ int   singles[MAXSPLIT], exh[MAXSPLIT];
    __shared__ int   nsing, nexh;
    __shared__ float wbv[4];
    __shared__ int   wbi[4];

    if (tid < nsp) {                    // coalesced [q][sp] records
        size_t rec = (size_t)q * MAXSPLIT + tid;
        sv1[tid] = g_b1v[rec];
        sv2[tid] = g_b2v[rec];
        si1[tid] = g_b1i[rec];
    }
    float rnq = g_rn[MAXV + q];
    const float* qr = qry + (size_t)q * DIMK;
    #pragma unroll
    for (int i = 0; i < 4; ++i) {
        int k = tid + i * 128;
        float m = g_mean[k];
        ms[k] = m;
        qc[k] = (qr[k] - m) * rnq;
    }
    __syncthreads();
    if (tid == 0) {
        float mx = -FLT_MAX;
        for (int sp = 0; sp < nsp; ++sp) mx = fmaxf(mx, sv1[sp]);
        float th = mx - TH;
        int a = 0, b = 0;
        for (int sp = 0; sp < nsp; ++sp) {
            if (sv1[sp] >= th) {
                if (sv2[sp] >= th) exh[b++] = sp;
                else singles[a++] = si1[sp];
            }
        }
        nsing = a; nexh = b;
    }
    __syncthreads();

    float bv = -FLT_MAX;
    int   bi = MAXV;

    for (int ci = warp; ci < nsing; ci += 4) {
        int s = singles[ci];
        const float* sr = sup + (size_t)s * DIMK;
        float rns = g_rn[s];
        float d = 0.0f;
        #pragma unroll
        for (int i = 0; i < 16; ++i) {
            int k = i * 32 + lane;
            d += qc[k] * ((sr[k] - ms[k]) * rns);
        }
        #pragma unroll
        for (int o = 16; o; o >>= 1) d += __shfl_xor_sync(0xffffffffu, d, o);
        if (d > bv || (d == bv && s < bi)) { bv = d; bi = s; }
    }
    for (int e = 0; e < nexh; ++e) {
        int sp = exh[e];
        int sb = sp * ST;
        int se = min(sb + ST, ns);
        for (int s = sb + warp; s < se; s += 4) {
            const float* sr = sup + (size_t)s * DIMK;
            float rns = g_rn[s];
            float d = 0.0f;
            #pragma unroll
            for (int i = 0; i < 16; ++i) {
                int k = i * 32 + lane;
                d += qc[k] * ((sr[k] - ms[k]) * rns);
            }
            #pragma unroll
            for (int o = 16; o; o >>= 1) d += __shfl_xor_sync(0xffffffffu, d, o);
            if (d > bv || (d == bv && s < bi)) { bv = d; bi = s; }
        }
    }
    if (lane == 0) { wbv[warp] = bv; wbi[warp] = bi; }
    __syncthreads();
    if (tid == 0) {
        float fv = wbv[0]; int fi = wbi[0];
        #pragma unroll
        for (int w = 1; w < 4; ++w) {
            if (wbv[w] > fv || (wbv[w] == fv && wbi[w] < fi)) { fv = wbv[w]; fi = wbi[w]; }
        }
        out[q] = (float)(fi / SHOTS);
    }
}

// ---------------------------------------------------------------------------
extern "C" void kernel_launch(void* const* d_in, const int* in_sizes, int n_in,
                              void* d_out, int out_size) {
    const float* sup = (const float*)d_in[0];   // support_features [1000,5,512]
    const float* qry = (const float*)d_in[1];   // query_features   [5000,512]
    // d_in[2] = use_cosine: ignored (decision is mathematically identical)

    int nsup = in_sizes[0] / DIMK;
    int nq   = in_sizes[1] / DIMK;
    if (nsup > MAXV) nsup = MAXV;
    if (nq   > MAXV) nq   = MAXV;
    if (nsup < 1) nsup = 1;
    if (nq   < 1) nq   = 1;
    if (nq > out_size) nq = out_size;

    k_mean_part<<<MEANBLK, 256>>>(sup, nsup);
    k_mean_final<<<1, 256>>>(1.0f / (float)nsup);

    k_pack<<<(2 * MAXV) / 8, 256>>>(sup, qry, nsup, nq);

    int grid_q = (nq + QT - 1) / QT;             // 40
    int nsp    = (nsup + ST - 1) / ST;           // 40
    if (nsp < 1) nsp = 1;
    if (nsp > MAXSPLIT) nsp = MAXSPLIT;

    cudaFuncSetAttribute(k_mma_best,
                         cudaFuncAttributeMaxDynamicSharedMemorySize, SM_TOTAL);
    dim3 grid(grid_q, nsp);
    k_mma_best<<<grid, 256, SM_TOTAL>>>(nq, nsup);

    int pick_grid = (out_size > nq) ? out_size : nq;
    k_pick<<<pick_grid, 128>>>((float*)d_out, sup, qry, nq, nsup, nsp);
}

// round 17
// speedup vs baseline: 1.7196x; 1.0998x over previous
#include <cuda_runtime.h>
#include <cuda_fp16.h>
#include <math.h>
#include <float.h>
#include <stdint.h>

// ---------------------------------------------------------------------------
// NCM few-shot classifier — approximate-then-verify tensor-core pipeline.
//   1) mean over support rows (2-stage deterministic, float4)
//   2) pack: center+normalize; fp16(hi) rows (K=512) + per-row inv-norm
//   3) GEMM: fp16 mma.sync m16n8k16 (r13 chassis) with hoisted staging
//      addresses; per-split TOP-2 (v1,i1,v2) per query
//   4) pick: sound threshold TH=2.5e-3 (> 2x worst-case fp16 error ~1.1e-3
//      on unit vectors); singles -> one exact fp32 rescore from RAW inputs;
//      rare dense splits -> full split rescore. Class = best/SHOTS (float32).
// ---------------------------------------------------------------------------

#define DIMK    512
#define KP      512
#define SHOTS   5
#define QT      128
#define ST      128
#define CH      64
#define NCHUNK  (KP / CH)     // 8
#define ROWB    144
#define MAXV    5120
#define MAXSPLIT 40
#define MEANBLK 64
#define TH      2.5e-3f

// dynamic smem layout (bytes)
#define SM_STAGE   36864
#define SM_BOFF    18432
#define SM_SV1     73728
#define SM_SI1     74752
#define SM_SV2     75776
#define SM_TOTAL   76800

__device__ __align__(16) float  g_part[MEANBLK][DIMK];
__device__ __align__(16) float  g_mean[DIMK];
__device__ __align__(16) __half g_qh[(size_t)MAXV * KP];
__device__ __align__(16) __half g_sh[(size_t)MAXV * KP];
__device__ __align__(16) float  g_rn[2 * MAXV];
__device__ __align__(16) float  g_b1v[(size_t)MAXV * MAXSPLIT];
__device__ __align__(16) int    g_b1i[(size_t)MAXV * MAXSPLIT];
__device__ __align__(16) float  g_b2v[(size_t)MAXV * MAXSPLIT];

// ---- PTX helpers -------------------------------------------------------------
__device__ __forceinline__ uint32_t smem_u32(const void* p) {
    uint32_t a;
    asm("{ .reg .u64 t; cvta.to.shared.u64 t, %1; cvt.u32.u64 %0, t; }"
        : "=r"(a) : "l"(p));
    return a;
}
__device__ __forceinline__ uint64_t gmem_u64(const void* p) {
    uint64_t g;
    asm("cvta.to.global.u64 %0, %1;" : "=l"(g) : "l"(p));
    return g;
}
__device__ __forceinline__ void cp16g(uint32_t dst, uint64_t gsrc) {
    asm volatile("cp.async.cg.shared.global [%0], [%1], 16;"
                 :: "r"(dst), "l"(gsrc) : "memory");
}
__device__ __forceinline__ void cp_commit() {
    asm volatile("cp.async.commit_group;" ::: "memory");
}
template <int N>
__device__ __forceinline__ void cp_wait() {
    asm volatile("cp.async.wait_group %0;" :: "n"(N) : "memory");
}
__device__ __forceinline__ void ldsm_x4(uint32_t& r0, uint32_t& r1,
                                        uint32_t& r2, uint32_t& r3, uint32_t a) {
    asm volatile("ldmatrix.sync.aligned.m8n8.x4.shared.b16 {%0,%1,%2,%3}, [%4];"
                 : "=r"(r0), "=r"(r1), "=r"(r2), "=r"(r3) : "r"(a));
}
__device__ __forceinline__ void mma16816(float* c, const uint32_t* a,
                                         uint32_t b0, uint32_t b1) {
    asm volatile(
        "mma.sync.aligned.m16n8k16.row.col.f32.f16.f16.f32 "
        "{%0,%1,%2,%3}, {%4,%5,%6,%7}, {%8,%9}, {%0,%1,%2,%3};"
        : "+f"(c[0]), "+f"(c[1]), "+f"(c[2]), "+f"(c[3])
        : "r"(a[0]), "r"(a[1]), "r"(a[2]), "r"(a[3]), "r"(b0), "r"(b1));
}

// --- stage 1/2: deterministic support mean (float4) -----------------------------
__global__ void k_mean_part(const float* __restrict__ s, int nrows) {
    int b = blockIdx.x, t = threadIdx.x;            // 128 threads, 1 float4 each
    float4 a = make_float4(0.f, 0.f, 0.f, 0.f);
    for (int r = b; r < nrows; r += MEANBLK) {
        float4 v = ((const float4*)(s + (size_t)r * DIMK))[t];
        a.x += v.x; a.y += v.y; a.z += v.z; a.w += v.w;
    }
    ((float4*)g_part[b])[t] = a;
}
__global__ void k_mean_final(float inv_cnt) {
    int t = threadIdx.x;                            // 128 threads
    float4 a = make_float4(0.f, 0.f, 0.f, 0.f);
    #pragma unroll 8
    for (int b = 0; b < MEANBLK; ++b) {
        float4 v = ((const float4*)g_part[b])[t];
        a.x += v.x; a.y += v.y; a.z += v.z; a.w += v.w;
    }
    a.x *= inv_cnt; a.y *= inv_cnt; a.z *= inv_cnt; a.w *= inv_cnt;
    ((float4*)g_mean)[t] = a;
}

// --- stage 3: center + normalize; fp16(hi) rows + inv-norm (float4) -------------
__global__ void k_pack(const float* __restrict__ sup, const float* __restrict__ qry,
                       int nsup, int nq) {
    int gw   = blockIdx.x * 8 + (threadIdx.x >> 5);
    int lane = threadIdx.x & 31;
    if (gw >= 2 * MAXV) return;
    bool isQ = (gw >= MAXV);
    int  row = isQ ? gw - MAXV : gw;
    __half* dh = (isQ ? g_qh : g_sh) + (size_t)row * KP;
    bool valid = isQ ? (row < nq) : (row < nsup);
    if (!valid) {                          // zero fp16 pad rows (MMA operands)
        uint4 z = make_uint4(0, 0, 0, 0);
        ((uint4*)dh)[lane] = z;
        ((uint4*)dh)[lane + 32] = z;
        return;
    }
    const float4* src4 = (const float4*)((isQ ? qry : sup) + (size_t)row * DIMK);
    const float4* m4   = (const float4*)g_mean;
    float4 vv[4];
    float nrm = 0.0f;
    #pragma unroll
    for (int i = 0; i < 4; ++i) {
        int k4 = i * 32 + lane;
        float4 v = src4[k4];
        float4 m = m4[k4];
        v.x -= m.x; v.y -= m.y; v.z -= m.z; v.w -= m.w;
        nrm += v.x * v.x + v.y * v.y + v.z * v.z + v.w * v.w;
        vv[i] = v;
    }
    #pragma unroll
    for (int o = 16; o; o >>= 1) nrm += __shfl_xor_sync(0xffffffffu, nrm, o);
    float rn = 1.0f / sqrtf(nrm);
    #pragma unroll
    for (int i = 0; i < 4; ++i) {
        int k4 = i * 32 + lane;
        __half2 h01 = __floats2half2_rn(vv[i].x * rn, vv[i].y * rn);
        __half2 h23 = __floats2half2_rn(vv[i].z * rn, vv[i].w * rn);
        uint2 st;
        st.x = *(uint32_t*)&h01;
        st.y = *(uint32_t*)&h23;
        *(uint2*)(dh + 4 * k4) = st;
    }
    if (lane == 0) g_rn[isQ ? (MAXV + row) : row] = rn;
}

// --- stage 4: mma.sync GEMM (128x128) + per-split TOP-2 epilogue ----------------
__global__ void __launch_bounds__(256, 2)
k_mma_best(int nq, int ns) {
    extern __shared__ __align__(16) char smem[];
    const uint32_t sb = smem_u32(smem);
    const int tid   = threadIdx.x;
    const int lane  = tid & 31;
    const int warp  = tid >> 5;
    const int warpm = warp >> 1;
    const int warpn = warp & 1;
    const int q0    = blockIdx.x * QT;
    const int sbeg  = blockIdx.y * ST;

    // hoisted staging addresses: thread owns rows r0+{0,32,64,96}, byte-col p*16
    const int r0 = tid >> 3;
    const int p  = tid & 7;
    const uint64_t gA = gmem_u64(g_qh + (size_t)(q0 + r0) * KP + p * 8);
    const uint64_t gB = gmem_u64(g_sh + (size_t)(sbeg + r0) * KP + p * 8);
    const uint32_t dA = sb + r0 * ROWB + p * 16;

    #define STAGE(buf_, ko_) do {                                             \
        uint32_t _a = dA + (buf_) * SM_STAGE;                                 \
        uint32_t _b = _a + SM_BOFF;                                           \
        _Pragma("unroll")                                                     \
        for (int _l = 0; _l < 4; ++_l) {                                      \
            cp16g(_a + _l * (32 * ROWB), gA + (uint64_t)(_l * 32768 + (ko_)));\
            cp16g(_b + _l * (32 * ROWB), gB + (uint64_t)(_l * 32768 + (ko_)));\
        }                                                                     \
    } while (0)

    float acc[2][8][4];
    #pragma unroll
    for (int mt = 0; mt < 2; ++mt)
        #pragma unroll
        for (int nt = 0; nt < 8; ++nt)
            #pragma unroll
            for (int e = 0; e < 4; ++e) acc[mt][nt][e] = 0.0f;

    STAGE(0, 0);
    cp_commit();

    const int r = lane & 7, g = lane >> 3;
    const int m0 = warpm * 32, n0 = warpn * 64;

    for (int kc = 0; kc < NCHUNK; ++kc) {
        const int cur = kc & 1;
        if (kc + 1 < NCHUNK) {
            STAGE(cur ^ 1, (kc + 1) * 128);
            cp_commit();
            cp_wait<1>();
        } else {
            cp_wait<0>();
        }
        __syncthreads();

        uint32_t ab = sb + cur * SM_STAGE;
        uint32_t bb = ab + SM_BOFF;
        #pragma unroll
        for (int ks = 0; ks < 4; ++ks) {
            const int k0 = ks * 16;
            uint32_t a[2][4];
            #pragma unroll
            for (int mt = 0; mt < 2; ++mt) {
                uint32_t addr = ab + (m0 + mt * 16 + ((g & 1) << 3) + r) * ROWB
                                   + (k0 + ((g >> 1) << 3)) * 2;
                ldsm_x4(a[mt][0], a[mt][1], a[mt][2], a[mt][3], addr);
            }
            #pragma unroll
            for (int np = 0; np < 4; ++np) {
                uint32_t b0, b1, b2, b3;
                uint32_t addr = bb + (n0 + np * 16 + ((g >> 1) << 3) + r) * ROWB
                                   + (k0 + ((g & 1) << 3)) * 2;
                ldsm_x4(b0, b1, b2, b3, addr);
                #pragma unroll
                for (int mt = 0; mt < 2; ++mt) {
                    mma16816(acc[mt][np * 2 + 0], a[mt], b0, b1);
                    mma16816(acc[mt][np * 2 + 1], a[mt], b2, b3);
                }
            }
        }
        __syncthreads();
    }
    #undef STAGE

    // ---- epilogue: per-lane TOP-2 per owned row --------------------------------
    const int group = lane >> 2, tg = lane & 3;
    float v1[4], v2[4];
    int   i1[4];
    #pragma unroll
    for (int i = 0; i < 4; ++i) { v1[i] = -FLT_MAX; v2[i] = -FLT_MAX; i1[i] = MAXV; }

    #pragma unroll
    for (int mt = 0; mt < 2; ++mt)
        #pragma unroll
        for (int nt = 0; nt < 8; ++nt) {
            int c0 = sbeg + n0 + nt * 8 + tg * 2;
            #pragma unroll
            for (int h = 0; h < 2; ++h) {
                int i = mt * 2 + h;
                float a0 = acc[mt][nt][h * 2 + 0];
                float a1 = acc[mt][nt][h * 2 + 1];
                if (c0 < ns) {
                    if (a0 > v1[i]) { v2[i] = v1[i]; v1[i] = a0; i1[i] = c0; }
                    else if (a0 > v2[i]) v2[i] = a0;
                }
                if (c0 + 1 < ns) {
                    if (a1 > v1[i]) { v2[i] = v1[i]; v1[i] = a1; i1[i] = c0 + 1; }
                    else if (a1 > v2[i]) v2[i] = a1;
                }
            }
        }
    #pragma unroll
    for (int o = 1; o < 4; o <<= 1) {
        #pragma unroll
        for (int i = 0; i < 4; ++i) {
            float ov1 = __shfl_xor_sync(0xffffffffu, v1[i], o);
            int   oi1 = __shfl_xor_sync(0xffffffffu, i1[i], o);
            float ov2 = __shfl_xor_sync(0xffffffffu, v2[i], o);
            if (ov1 > v1[i] || (ov1 == v1[i] && oi1 < i1[i])) {
                v2[i] = fmaxf(v1[i], ov2); v1[i] = ov1; i1[i] = oi1;
            } else {
                v2[i] = fmaxf(v2[i], ov1);
            }
        }
    }
    float* s_v1 = (float*)(smem + SM_SV1);   // [128][2]
    int*   s_i1 = (int*)(smem + SM_SI1);
    float* s_v2 = (float*)(smem + SM_SV2);
    if (tg == 0) {
        #pragma unroll
        for (int mt = 0; mt < 2; ++mt)
            #pragma unroll
            for (int h = 0; h < 2; ++h) {
                int row = m0 + mt * 16 + h * 8 + group;
                s_v1[row * 2 + warpn] = v1[mt * 2 + h];
                s_i1[row * 2 + warpn] = i1[mt * 2 + h];
                s_v2[row * 2 + warpn] = v2[mt * 2 + h];
            }
    }
    __syncthreads();
    if (tid < QT) {
        float a1v = s_v1[tid * 2 + 0], a2v = s_v2[tid * 2 + 0];
        int   a1i = s_i1[tid * 2 + 0];
        float b1v = s_v1[tid * 2 + 1], b2v = s_v2[tid * 2 + 1];
        int   b1i = s_i1[tid * 2 + 1];
        float o1, o2; int oi;
        if (b1v > a1v || (b1v == a1v && b1i < a1i)) {
            o1 = b1v; oi = b1i; o2 = fmaxf(a1v, b2v);
        } else {
            o1 = a1v; oi = a1i; o2 = fmaxf(a2v, b1v);
        }
        int q = q0 + tid;
        if (q < nq) {
            size_t rec = (size_t)q * MAXSPLIT + blockIdx.y;
            g_b1v[rec] = o1;
            g_b1i[rec] = oi;
            g_b2v[rec] = o2;
        }
    }
}

// --- stage 5: pick — threshold, exact fp32 rescore from RAW inputs --------------
__global__ void __launch_bounds__(128)
k_pick(float* __restrict__ out,
       const float* __restrict__ sup, const float* __restrict__ qry,
       int nq, int ns, int nsp) {
    int q = blockIdx.x;
    const int tid  = threadIdx.x;
    if (q >= nq) { if (tid == 0) out[q] = 0.0f; return; }
    const int lane = tid & 31;
    const int warp = tid >> 5;

    __shared__ __align__(16) float ms[DIMK];   // mean
    __shared__ __align__(16) float qc[DIMK];   // (q - m) * rnq
    __shared__ float sv1[MAXSPLIT], sv2[MAXSPLIT];
    __shared__ int   si1[MAXSPLIT];
    __shared__ int   singles[MAXSPLIT], exh[MAXSPLIT];
    __shared__ int   nsing, nexh;
    __shared__ float wbv[4];
    __shared__ int   wbi[4];

    if (tid < nsp) {
        size_t rec = (size_t)q * MAXSPLIT + tid;
        sv1[tid] = g_b1v[rec];
        sv2[tid] = g_b2v[rec];
        si1[tid] = g_b1i[rec];
    }
    float rnq = g_rn[MAXV + q];
    {
        const float4* qr4 = (const float4*)(qry + (size_t)q * DIMK);
        const float4* m4  = (const float4*)g_mean;
        #pragma unroll
        for (int i = 0; i < 1; ++i) {
            int k4 = tid;                      // 128 threads x 1 float4 = 512
            float4 m = m4[k4];
            float4 v = qr4[k4];
            ((float4*)ms)[k4] = m;
            float4 c;
            c.x = (v.x - m.x) * rnq; c.y = (v.y - m.y) * rnq;
            c.z = (v.z - m.z) * rnq; c.w = (v.w - m.w) * rnq;
            ((float4*)qc)[k4] = c;
        }
    }
    __syncthreads();
    if (tid == 0) {
        float mx = -FLT_MAX;
        for (int sp = 0; sp < nsp; ++sp) mx = fmaxf(mx, sv1[sp]);
        float th = mx - TH;
        int a = 0, b = 0;
        for (int sp = 0; sp < nsp; ++sp) {
            if (sv1[sp] >= th) {
                if (sv2[sp] >= th) exh[b++] = sp;
                else singles[a++] = si1[sp];
            }
        }
        nsing = a; nexh = b;
    }
    __syncthreads();

    float bv = -FLT_MAX;
    int   bi = MAXV;

    for (int ci = warp; ci < nsing; ci += 4) {
        int s = singles[ci];
        const float4* sr4 = (const float4*)(sup + (size_t)s * DIMK);
        float rns = g_rn[s];
        float d = 0.0f;
        #pragma unroll
        for (int i = 0; i < 4; ++i) {
            int k4 = i * 32 + lane;
            float4 sv = sr4[k4];
            float4 m4 = ((const float4*)ms)[k4];
            float4 c4 = ((const float4*)qc)[k4];
            d += c4.x * ((sv.x - m4.x) * rns) + c4.y * ((sv.y - m4.y) * rns)
               + c4.z * ((sv.z - m4.z) * rns) + c4.w * ((sv.w - m4.w) * rns);
        }
        #pragma unroll
        for (int o = 16; o; o >>= 1) d += __shfl_xor_sync(0xffffffffu, d, o);
        if (d > bv || (d == bv && s < bi)) { bv = d; bi = s; }
    }
    for (int e = 0; e < nexh; ++e) {
        int sp = exh[e];
        int sb = sp * ST;
        int se = min(sb + ST, ns);
        for (int s = sb + warp; s < se; s += 4) {
            const float4* sr4 = (const float4*)(sup + (size_t)s * DIMK);
            float rns = g_rn[s];
            float d = 0.0f;
            #pragma unroll
            for (int i = 0; i < 4; ++i) {
                int k4 = i * 32 + lane;
                float4 sv = sr4[k4];
                float4 m4 = ((const float4*)ms)[k4];
                float4 c4 = ((const float4*)qc)[k4];
                d += c4.x * ((sv.x - m4.x) * rns) + c4.y * ((sv.y - m4.y) * rns)
                   + c4.z * ((sv.z - m4.z) * rns) + c4.w * ((sv.w - m4.w) * rns);
            }
            #pragma unroll
            for (int o = 16; o; o >>= 1) d += __shfl_xor_sync(0xffffffffu, d, o);
            if (d > bv || (d == bv && s < bi)) { bv = d; bi = s; }
        }
    }
    if (lane == 0) { wbv[warp] = bv; wbi[warp] = bi; }
    __syncthreads();
    if (tid == 0) {
        float fv = wbv[0]; int fi = wbi[0];
        #pragma unroll
        for (int w = 1; w < 4; ++w) {
            if (wbv[w] > fv || (wbv[w] == fv && wbi[w] < fi)) { fv = wbv[w]; fi = wbi[w]; }
        }
        out[q] = (float)(fi / SHOTS);
    }
}

// ---------------------------------------------------------------------------
extern "C" void kernel_launch(void* const* d_in, const int* in_sizes, int n_in,
                              void* d_out, int out_size) {
    const float* sup = (const float*)d_in[0];   // support_features [1000,5,512]
    const float* qry = (const float*)d_in[1];   // query_features   [5000,512]
    // d_in[2] = use_cosine: ignored (decision is mathematically identical)

    int nsup = in_sizes[0] / DIMK;
    int nq   = in_sizes[1] / DIMK;
    if (nsup > MAXV) nsup = MAXV;
    if (nq   > MAXV) nq   = MAXV;
    if (nsup < 1) nsup = 1;
    if (nq   < 1) nq   = 1;
    if (nq > out_size) nq = out_size;

    k_mean_part<<<MEANBLK, 128>>>(sup, nsup);
    k_mean_final<<<1, 128>>>(1.0f / (float)nsup);

    k_pack<<<(2 * MAXV) / 8, 256>>>(sup, qry, nsup, nq);

    int grid_q = (nq + QT - 1) / QT;             // 40
    int nsp    = (nsup + ST - 1) / ST;           // 40
    if (nsp < 1) nsp = 1;
    if (nsp > MAXSPLIT) nsp = MAXSPLIT;

    cudaFuncSetAttribute(k_mma_best,
                         cudaFuncAttributeMaxDynamicSharedMemorySize, SM_TOTAL);
    dim3 grid(grid_q, nsp);
    k_mma_best<<<grid, 256, SM_TOTAL>>>(nq, nsup);

    int pick_grid = (out_size > nq) ? out_size : nq;
    k_pick<<<pick_grid, 128>>>((float*)d_out, sup, qry, nq, nsup, nsp);
}